// round 3
// baseline (speedup 1.0000x reference)
#include <cuda_runtime.h>
#include <cuda_bf16.h>

// Problem constants
#define NN 50000      // nodes
#define NE 800000     // edges
#define HEADS 4
#define CH 64
#define F 256         // HEADS*CH == input dim for both layers

// ---------------- scratch (device globals; no allocation allowed) ----------------
__device__ float g_h[NN * F];       // post-GEMM features of current layer
__device__ float g_acc[NN * F];     // weighted-message accumulator (numerator)
__device__ float g_feat[NN * F];    // layer-1 output / layer-2 input
__device__ float g_asrc[NN * HEADS];
__device__ float g_adst[NN * HEADS];
__device__ float g_denom[NN * HEADS];
__device__ float g_ew[NE * HEADS];  // per-edge exp(leaky_relu(e)) weights

// ---------------- helpers ----------------
__device__ __forceinline__ float lrelu(float x) { return x > 0.f ? x : 0.2f * x; }
__device__ __forceinline__ float elu1(float x)  { return x > 0.f ? x : expf(x) - 1.f; }

__device__ __forceinline__ void red_add_v4(float* addr, float4 v) {
    asm volatile("red.global.add.v4.f32 [%0], {%1,%2,%3,%4};"
                 :: "l"(addr), "f"(v.x), "f"(v.y), "f"(v.z), "f"(v.w)
                 : "memory");
}

// ---------------- GEMM: g_h = A[NN,256] @ B[256,256] ----------------
// 64x64 tile, BK=16, 256 threads, 4x4 microtile per thread.
// useFeat!=0 -> read A from g_feat (layer 2), else from Ax param.
__global__ void gemm_kernel(const float* __restrict__ Ax,
                            const float* __restrict__ B,
                            int useFeat) {
    __shared__ float Ast[16][64];   // [k][m]
    __shared__ float Bs[16][64];    // [k][n]

    const float* A = useFeat ? g_feat : Ax;

    int tid = threadIdx.x;          // 0..255
    int tx = tid & 15;              // 0..15 (N dir)
    int ty = tid >> 4;              // 0..15 (M dir)
    int row0 = blockIdx.y * 64;
    int col0 = blockIdx.x * 64;

    // load mapping
    int ar = tid >> 2;              // 0..63  : A row within tile
    int ak = (tid & 3) * 4;         // 0,4,8,12 : A k within tile (float4)
    int bkr = tid >> 4;             // 0..15  : B k row
    int bnc = (tid & 15) * 4;       // B n col (float4)

    float acc[4][4];
#pragma unroll
    for (int i = 0; i < 4; i++)
#pragma unroll
        for (int j = 0; j < 4; j++) acc[i][j] = 0.f;

    for (int k0 = 0; k0 < F; k0 += 16) {
        float4 av = make_float4(0.f, 0.f, 0.f, 0.f);
        int arow = row0 + ar;
        if (arow < NN) av = *(const float4*)&A[arow * F + k0 + ak];
        Ast[ak + 0][ar] = av.x;
        Ast[ak + 1][ar] = av.y;
        Ast[ak + 2][ar] = av.z;
        Ast[ak + 3][ar] = av.w;

        float4 bv = *(const float4*)&B[(k0 + bkr) * F + col0 + bnc];
        *(float4*)&Bs[bkr][bnc] = bv;

        __syncthreads();

#pragma unroll
        for (int kk = 0; kk < 16; kk++) {
            float4 a4 = *(float4*)&Ast[kk][ty * 4];
            float4 b4 = *(float4*)&Bs[kk][tx * 4];
            float a[4] = {a4.x, a4.y, a4.z, a4.w};
            float b[4] = {b4.x, b4.y, b4.z, b4.w};
#pragma unroll
            for (int i = 0; i < 4; i++)
#pragma unroll
                for (int j = 0; j < 4; j++) acc[i][j] += a[i] * b[j];
        }
        __syncthreads();
    }

#pragma unroll
    for (int i = 0; i < 4; i++) {
        int row = row0 + ty * 4 + i;
        if (row < NN) {
            float4 v = make_float4(acc[i][0], acc[i][1], acc[i][2], acc[i][3]);
            *(float4*)&g_h[row * F + col0 + tx * 4] = v;
        }
    }
}

// ---------------- attention coefficients: a_src, a_dst per (node, head) ----------------
__global__ void attn_kernel(const float* __restrict__ att_src,
                            const float* __restrict__ att_dst) {
    int idx = blockIdx.x * blockDim.x + threadIdx.x;
    if (idx >= NN * HEADS) return;
    int n = idx >> 2;
    int h = idx & 3;
    const float4* hp = (const float4*)&g_h[n * F + h * CH];
    const float4* as = (const float4*)&att_src[h * CH];
    const float4* ad = (const float4*)&att_dst[h * CH];
    float ssum = 0.f, dsum = 0.f;
#pragma unroll
    for (int i = 0; i < 16; i++) {
        float4 v = hp[i];
        float4 s4 = as[i];
        float4 d4 = ad[i];
        ssum += v.x * s4.x + v.y * s4.y + v.z * s4.z + v.w * s4.w;
        dsum += v.x * d4.x + v.y * d4.y + v.z * d4.z + v.w * d4.w;
    }
    g_asrc[idx] = ssum;
    g_adst[idx] = dsum;
}

// ---------------- node init: self-loop contribution (denom + acc) ----------------
__global__ void node_init_kernel() {
    int idx = blockIdx.x * blockDim.x + threadIdx.x;
    if (idx >= NN * HEADS) return;
    int n = idx >> 2;
    int h = idx & 3;
    float a = lrelu(g_asrc[idx] + g_adst[idx]);
    float w = expf(a);
    g_denom[idx] = w;
    const float4* hp = (const float4*)&g_h[n * F + h * CH];
    float4* ap = (float4*)&g_acc[n * F + h * CH];
#pragma unroll
    for (int i = 0; i < 16; i++) {
        float4 v = hp[i];
        v.x *= w; v.y *= w; v.z *= w; v.w *= w;
        ap[i] = v;
    }
}

// ---------------- edge weights: w[e][h] = exp(lrelu(asrc[src]+adst[dst])), denom += w ----------------
__global__ void edge_w_kernel(const int* __restrict__ src,
                              const int* __restrict__ dst) {
    int e = blockIdx.x * blockDim.x + threadIdx.x;
    if (e >= NE) return;
    int s = src[e];
    int d = dst[e];
    float4 as = *(const float4*)&g_asrc[s * 4];
    float4 ad = *(const float4*)&g_adst[d * 4];
    float4 w;
    w.x = expf(lrelu(as.x + ad.x));
    w.y = expf(lrelu(as.y + ad.y));
    w.z = expf(lrelu(as.z + ad.z));
    w.w = expf(lrelu(as.w + ad.w));
    *(float4*)&g_ew[e * 4] = w;
    red_add_v4(&g_denom[d * 4], w);
}

// ---------------- edge aggregation: acc[dst] += w * h[src], warp per edge ----------------
__global__ void edge_agg_kernel(const int* __restrict__ src,
                                const int* __restrict__ dst) {
    int gid = blockIdx.x * blockDim.x + threadIdx.x;
    int e = gid >> 5;
    int lane = gid & 31;
    if (e >= NE) return;
    int s = src[e];
    int d = dst[e];
    int h = lane >> 3;                 // lane*8 / 64
    float w = g_ew[e * 4 + h];
    const float4* hp = (const float4*)&g_h[s * F + lane * 8];
    float4 v0 = hp[0];
    float4 v1 = hp[1];
    v0.x *= w; v0.y *= w; v0.z *= w; v0.w *= w;
    v1.x *= w; v1.y *= w; v1.z *= w; v1.w *= w;
    float* base = &g_acc[d * F + lane * 8];
    red_add_v4(base, v0);
    red_add_v4(base + 4, v1);
}

// ---------------- finalize: out = elu(acc/denom + bias) ----------------
// toFeat!=0 -> write g_feat (layer 1), else write outp (layer 2).
__global__ void finalize_kernel(const float* __restrict__ bias,
                                float* __restrict__ outp,
                                int toFeat) {
    int idx = blockIdx.x * blockDim.x + threadIdx.x;
    if (idx >= NN * 64) return;          // one float4 per thread
    int n = idx >> 6;
    int q = idx & 63;
    int h = q >> 4;
    float4 v = *(float4*)&g_acc[n * F + q * 4];
    float inv = 1.f / (g_denom[n * 4 + h] + 1e-16f);
    float4 b = *(const float4*)&bias[q * 4];
    v.x = elu1(v.x * inv + b.x);
    v.y = elu1(v.y * inv + b.y);
    v.z = elu1(v.z * inv + b.z);
    v.w = elu1(v.w * inv + b.w);
    float* dstp = toFeat ? &g_feat[n * F + q * 4] : &outp[n * F + q * 4];
    *(float4*)dstp = v;
}

// ---------------- launch ----------------
static void run_layer(const float* x_or_null, int useFeat,
                      const float* W, const float* att_src, const float* att_dst,
                      const float* bias, const int* src, const int* dst,
                      float* outp, int toFeat) {
    dim3 gemmGrid(F / 64, (NN + 63) / 64);
    gemm_kernel<<<gemmGrid, 256>>>(x_or_null, W, useFeat);

    int nh = NN * HEADS;
    attn_kernel<<<(nh + 255) / 256, 256>>>(att_src, att_dst);
    node_init_kernel<<<(nh + 255) / 256, 256>>>();
    edge_w_kernel<<<(NE + 255) / 256, 256>>>(src, dst);
    edge_agg_kernel<<<(NE * 32 + 255) / 256, 256>>>(src, dst);
    finalize_kernel<<<(NN * 64 + 255) / 256, 256>>>(bias, outp, toFeat);
}

extern "C" void kernel_launch(void* const* d_in, const int* in_sizes, int n_in,
                              void* d_out, int out_size) {
    const float* x        = (const float*)d_in[0];
    const int*   ei       = (const int*)  d_in[1];
    const float* W1       = (const float*)d_in[2];
    const float* att_src1 = (const float*)d_in[3];
    const float* att_dst1 = (const float*)d_in[4];
    const float* b1       = (const float*)d_in[5];
    const float* W2       = (const float*)d_in[6];
    const float* att_src2 = (const float*)d_in[7];
    const float* att_dst2 = (const float*)d_in[8];
    const float* b2       = (const float*)d_in[9];
    float* out = (float*)d_out;

    const int* src = ei;            // edge_index[0]
    const int* dst = ei + NE;       // edge_index[1]

    // layer 1: x -> g_feat
    run_layer(x, 0, W1, att_src1, att_dst1, b1, src, dst, nullptr, 1);
    // layer 2: g_feat -> out
    run_layer(nullptr, 1, W2, att_src2, att_dst2, b2, src, dst, out, 0);
}

// round 7
// speedup vs baseline: 1.1302x; 1.1302x over previous
#include <cuda_runtime.h>
#include <cuda_bf16.h>
#include <cstdint>

// Problem constants
#define NN 50000      // nodes
#define NE 800000     // edges
#define HEADS 4
#define CH 64
#define F 256         // HEADS*CH == input dim for both layers

// GEMM tiling
#define BM 128
#define BN 128
#define BK 16

// ---------------- scratch (device globals; no allocation allowed) ----------------
__device__ float g_h[NN * F];       // post-GEMM features of current layer
__device__ float g_acc[NN * F];     // weighted-message accumulator (numerator)
__device__ float g_feat[NN * F];    // layer-1 output / layer-2 input
__device__ float g_asrc[NN * HEADS];
__device__ float g_adst[NN * HEADS];
__device__ float g_denom[NN * HEADS];
__device__ float g_ew[NE * HEADS];  // per-edge exp(leaky_relu(e)) weights

// ---------------- helpers ----------------
__device__ __forceinline__ float lrelu(float x) { return x > 0.f ? x : 0.2f * x; }
__device__ __forceinline__ float elu1(float x)  { return x > 0.f ? x : expf(x) - 1.f; }

__device__ __forceinline__ void red_add_v4(float* addr, float4 v) {
    asm volatile("red.global.add.v4.f32 [%0], {%1,%2,%3,%4};"
                 :: "l"(addr), "f"(v.x), "f"(v.y), "f"(v.z), "f"(v.w)
                 : "memory");
}

// tf32 mma: D += A(16x8, row) * B(8x8, col), fp32 accum
__device__ __forceinline__ void mma_tf32(float* d, const uint32_t* a, const uint32_t* b) {
    asm volatile(
        "mma.sync.aligned.m16n8k8.row.col.f32.tf32.tf32.f32 "
        "{%0,%1,%2,%3}, {%4,%5,%6,%7}, {%8,%9}, {%0,%1,%2,%3};"
        : "+f"(d[0]), "+f"(d[1]), "+f"(d[2]), "+f"(d[3])
        : "r"(a[0]), "r"(a[1]), "r"(a[2]), "r"(a[3]), "r"(b[0]), "r"(b[1]));
}

// split fp32 into tf32 hi + tf32 lo (truncation; lo*lo term ~2^-22, dropped)
__device__ __forceinline__ void tf32_split(float f, uint32_t& hi, uint32_t& lo) {
    hi = __float_as_uint(f) & 0xFFFFE000u;
    float lf = f - __uint_as_float(hi);
    lo = __float_as_uint(lf) & 0xFFFFE000u;
}

// ---------------- GEMM: g_h = A[NN,256] @ B[256,256] via 3xTF32 tensor cores --------
// 128x128 block tile, BK=16, 256 threads (8 warps, 4x2), warp tile 32x64.
// XOR-swizzled SMEM [k][m] / [k][n] for conflict-free fragment loads.
__global__ void __launch_bounds__(256, 1)
gemm_tf32_kernel(const float* __restrict__ Ax, const float* __restrict__ B, int useFeat) {
    __shared__ float As[BK * BM];
    __shared__ float Bs[BK * BN];

    const float* A = useFeat ? g_feat : Ax;

    int tid  = threadIdx.x;
    int warp = tid >> 5;
    int lane = tid & 31;
    int wm = warp >> 1;              // 0..3
    int wn = warp & 1;               // 0..1
    int row0 = blockIdx.y * BM;
    int col0 = blockIdx.x * BN;
    int c = lane & 3;                // quad column
    int r = lane >> 2;               // quad row (0..7)

    float acc[2][8][4];
#pragma unroll
    for (int mt = 0; mt < 2; mt++)
#pragma unroll
        for (int nt = 0; nt < 8; nt++)
#pragma unroll
            for (int i = 0; i < 4; i++) acc[mt][nt][i] = 0.f;

    // ---- gmem load mapping ----
    int am = tid >> 1;               // A row within tile (0..127)
    int ak = (tid & 1) * 8;          // A k offset (0 or 8)
    int bk = tid >> 4;               // B k row (0..15)
    int bn = (tid & 15) * 8;         // B n offset (0..120, step 8)

    float4 pa0, pa1, pb0, pb1;
    {
        int grow = row0 + am;
        if (grow < NN) {
            pa0 = *(const float4*)&A[grow * F + ak];
            pa1 = *(const float4*)&A[grow * F + ak + 4];
        } else {
            pa0 = make_float4(0.f, 0.f, 0.f, 0.f);
            pa1 = pa0;
        }
        pb0 = *(const float4*)&B[bk * F + col0 + bn];
        pb1 = *(const float4*)&B[bk * F + col0 + bn + 4];
    }

    for (int k0 = 0; k0 < F; k0 += BK) {
        // store current tile to smem (A transposed + swizzled)
        float av[8] = {pa0.x, pa0.y, pa0.z, pa0.w, pa1.x, pa1.y, pa1.z, pa1.w};
#pragma unroll
        for (int j = 0; j < 8; j++) {
            int kk = ak + j;
            As[kk * BM + (am ^ ((kk & 3) << 3))] = av[j];
        }
        *(float4*)&Bs[bk * BN + (bn ^ ((bk & 3) << 3))]       = pb0;
        *(float4*)&Bs[bk * BN + ((bn + 4) ^ ((bk & 3) << 3))] = pb1;
        __syncthreads();

        // prefetch next tile
        if (k0 + BK < F) {
            int kn = k0 + BK;
            int grow = row0 + am;
            if (grow < NN) {
                pa0 = *(const float4*)&A[grow * F + kn + ak];
                pa1 = *(const float4*)&A[grow * F + kn + ak + 4];
            } else {
                pa0 = make_float4(0.f, 0.f, 0.f, 0.f);
                pa1 = pa0;
            }
            pb0 = *(const float4*)&B[(kn + bk) * F + col0 + bn];
            pb1 = *(const float4*)&B[(kn + bk) * F + col0 + bn + 4];
        }

        // compute: two k8 steps
#pragma unroll
        for (int k8 = 0; k8 < 2; k8++) {
            int kb = k8 * 8;
            uint32_t aH[2][4], aL[2][4];
#pragma unroll
            for (int mt = 0; mt < 2; mt++) {
                int m0 = wm * 32 + mt * 16;
                int xr  = (m0 + r) ^ (c << 3);
                int xr8 = (m0 + r + 8) ^ (c << 3);
                float f0 = As[(kb + c) * BM + xr];
                float f1 = As[(kb + c) * BM + xr8];
                float f2 = As[(kb + c + 4) * BM + xr];
                float f3 = As[(kb + c + 4) * BM + xr8];
                tf32_split(f0, aH[mt][0], aL[mt][0]);
                tf32_split(f1, aH[mt][1], aL[mt][1]);
                tf32_split(f2, aH[mt][2], aL[mt][2]);
                tf32_split(f3, aH[mt][3], aL[mt][3]);
            }
#pragma unroll
            for (int nt = 0; nt < 8; nt++) {
                int n_ = wn * 64 + nt * 8 + r;
                int xn = n_ ^ (c << 3);
                float g0 = Bs[(kb + c) * BN + xn];
                float g1 = Bs[(kb + c + 4) * BN + xn];
                uint32_t bH[2], bL[2];
                tf32_split(g0, bH[0], bL[0]);
                tf32_split(g1, bH[1], bL[1]);
#pragma unroll
                for (int mt = 0; mt < 2; mt++) {
                    mma_tf32(acc[mt][nt], aH[mt], bH);
                    mma_tf32(acc[mt][nt], aH[mt], bL);
                    mma_tf32(acc[mt][nt], aL[mt], bH);
                }
            }
        }
        __syncthreads();
    }

    // epilogue -> g_h
#pragma unroll
    for (int mt = 0; mt < 2; mt++) {
        int rb = row0 + wm * 32 + mt * 16 + r;
#pragma unroll
        for (int nt = 0; nt < 8; nt++) {
            int cb = col0 + wn * 64 + nt * 8 + 2 * c;
            if (rb < NN)
                *(float2*)&g_h[rb * F + cb] = make_float2(acc[mt][nt][0], acc[mt][nt][1]);
            if (rb + 8 < NN)
                *(float2*)&g_h[(rb + 8) * F + cb] = make_float2(acc[mt][nt][2], acc[mt][nt][3]);
        }
    }
}

// ---------------- attention coefficients: a_src, a_dst per (node, head) ----------------
__global__ void attn_kernel(const float* __restrict__ att_src,
                            const float* __restrict__ att_dst) {
    int idx = blockIdx.x * blockDim.x + threadIdx.x;
    if (idx >= NN * HEADS) return;
    int n = idx >> 2;
    int h = idx & 3;
    const float4* hp = (const float4*)&g_h[n * F + h * CH];
    const float4* as = (const float4*)&att_src[h * CH];
    const float4* ad = (const float4*)&att_dst[h * CH];
    float ssum = 0.f, dsum = 0.f;
#pragma unroll
    for (int i = 0; i < 16; i++) {
        float4 v = hp[i];
        float4 s4 = as[i];
        float4 d4 = ad[i];
        ssum += v.x * s4.x + v.y * s4.y + v.z * s4.z + v.w * s4.w;
        dsum += v.x * d4.x + v.y * d4.y + v.z * d4.z + v.w * d4.w;
    }
    g_asrc[idx] = ssum;
    g_adst[idx] = dsum;
}

// ---------------- node init: self-loop contribution (denom + acc) ----------------
__global__ void node_init_kernel() {
    int idx = blockIdx.x * blockDim.x + threadIdx.x;
    if (idx >= NN * HEADS) return;
    int n = idx >> 2;
    int h = idx & 3;
    float a = lrelu(g_asrc[idx] + g_adst[idx]);
    float w = expf(a);
    g_denom[idx] = w;
    const float4* hp = (const float4*)&g_h[n * F + h * CH];
    float4* ap = (float4*)&g_acc[n * F + h * CH];
#pragma unroll
    for (int i = 0; i < 16; i++) {
        float4 v = hp[i];
        v.x *= w; v.y *= w; v.z *= w; v.w *= w;
        ap[i] = v;
    }
}

// ---------------- edge weights: w[e][h] = exp(lrelu(asrc[src]+adst[dst])), denom += w ----------------
__global__ void edge_w_kernel(const int* __restrict__ src,
                              const int* __restrict__ dst) {
    int e = blockIdx.x * blockDim.x + threadIdx.x;
    if (e >= NE) return;
    int s = src[e];
    int d = dst[e];
    float4 as = *(const float4*)&g_asrc[s * 4];
    float4 ad = *(const float4*)&g_adst[d * 4];
    float4 w;
    w.x = expf(lrelu(as.x + ad.x));
    w.y = expf(lrelu(as.y + ad.y));
    w.z = expf(lrelu(as.z + ad.z));
    w.w = expf(lrelu(as.w + ad.w));
    *(float4*)&g_ew[e * 4] = w;
    red_add_v4(&g_denom[d * 4], w);
}

// ---------------- edge aggregation: acc[dst] += w * h[src], warp per edge ----------------
__global__ void edge_agg_kernel(const int* __restrict__ src,
                                const int* __restrict__ dst) {
    int gid = blockIdx.x * blockDim.x + threadIdx.x;
    int e = gid >> 5;
    int lane = gid & 31;
    if (e >= NE) return;
    int s = src[e];
    int d = dst[e];
    int h = lane >> 3;                 // lane*8 / 64
    float w = g_ew[e * 4 + h];
    const float4* hp = (const float4*)&g_h[s * F + lane * 8];
    float4 v0 = hp[0];
    float4 v1 = hp[1];
    v0.x *= w; v0.y *= w; v0.z *= w; v0.w *= w;
    v1.x *= w; v1.y *= w; v1.z *= w; v1.w *= w;
    float* base = &g_acc[d * F + lane * 8];
    red_add_v4(base, v0);
    red_add_v4(base + 4, v1);
}

// ---------------- finalize: out = elu(acc/denom + bias) ----------------
__global__ void finalize_kernel(const float* __restrict__ bias,
                                float* __restrict__ outp,
                                int toFeat) {
    int idx = blockIdx.x * blockDim.x + threadIdx.x;
    if (idx >= NN * 64) return;          // one float4 per thread
    int n = idx >> 6;
    int q = idx & 63;
    int h = q >> 4;
    float4 v = *(float4*)&g_acc[n * F + q * 4];
    float inv = 1.f / (g_denom[n * 4 + h] + 1e-16f);
    float4 b = *(const float4*)&bias[q * 4];
    v.x = elu1(v.x * inv + b.x);
    v.y = elu1(v.y * inv + b.y);
    v.z = elu1(v.z * inv + b.z);
    v.w = elu1(v.w * inv + b.w);
    float* dstp = toFeat ? &g_feat[n * F + q * 4] : &outp[n * F + q * 4];
    *(float4*)dstp = v;
}

// ---------------- launch ----------------
static void run_layer(const float* x_or_null, int useFeat,
                      const float* W, const float* att_src, const float* att_dst,
                      const float* bias, const int* src, const int* dst,
                      float* outp, int toFeat) {
    dim3 gemmGrid(F / BN, (NN + BM - 1) / BM);
    gemm_tf32_kernel<<<gemmGrid, 256>>>(x_or_null, W, useFeat);

    int nh = NN * HEADS;
    attn_kernel<<<(nh + 255) / 256, 256>>>(att_src, att_dst);
    node_init_kernel<<<(nh + 255) / 256, 256>>>();
    edge_w_kernel<<<(NE + 255) / 256, 256>>>(src, dst);
    edge_agg_kernel<<<(NE * 32 + 255) / 256, 256>>>(src, dst);
    finalize_kernel<<<(NN * 64 + 255) / 256, 256>>>(bias, outp, toFeat);
}

extern "C" void kernel_launch(void* const* d_in, const int* in_sizes, int n_in,
                              void* d_out, int out_size) {
    const float* x        = (const float*)d_in[0];
    const int*   ei       = (const int*)  d_in[1];
    const float* W1       = (const float*)d_in[2];
    const float* att_src1 = (const float*)d_in[3];
    const float* att_dst1 = (const float*)d_in[4];
    const float* b1       = (const float*)d_in[5];
    const float* W2       = (const float*)d_in[6];
    const float* att_src2 = (const float*)d_in[7];
    const float* att_dst2 = (const float*)d_in[8];
    const float* b2       = (const float*)d_in[9];
    float* out = (float*)d_out;

    const int* src = ei;            // edge_index[0]
    const int* dst = ei + NE;       // edge_index[1]

    // layer 1: x -> g_feat
    run_layer(x, 0, W1, att_src1, att_dst1, b1, src, dst, nullptr, 1);
    // layer 2: g_feat -> out
    run_layer(nullptr, 1, W2, att_src2, att_dst2, b2, src, dst, out, 0);
}

// round 8
// speedup vs baseline: 2.0040x; 1.7732x over previous
#include <cuda_runtime.h>
#include <cuda_bf16.h>
#include <cstdint>

// Problem constants
#define NN 50000      // nodes
#define NE 800000     // edges
#define HEADS 4
#define CH 64
#define F 256         // HEADS*CH == input dim for both layers

// GEMM tiling
#define BM 128
#define BN 128
#define BK 16

// ---------------- scratch (device globals; no allocation allowed) ----------------
__device__ float g_h[NN * F];       // post-GEMM features of current layer
__device__ float g_feat[NN * F];    // layer-1 output / layer-2 input
__device__ float g_asrc[NN * HEADS];
__device__ float g_adst[NN * HEADS];
__device__ int   g_cnt[NN];         // in-degree histogram
__device__ int   g_start[NN + 1];   // CSR row starts (by dst)
__device__ int   g_cursor[NN];      // scatter cursors
__device__ int   g_csr_src[NE];     // src node id per CSR slot

// ---------------- helpers ----------------
__device__ __forceinline__ float lrelu(float x) { return x > 0.f ? x : 0.2f * x; }
__device__ __forceinline__ float elu1(float x)  { return x > 0.f ? x : expf(x) - 1.f; }

// tf32 mma: D += A(16x8, row) * B(8x8, col), fp32 accum
__device__ __forceinline__ void mma_tf32(float* d, const uint32_t* a, const uint32_t* b) {
    asm volatile(
        "mma.sync.aligned.m16n8k8.row.col.f32.tf32.tf32.f32 "
        "{%0,%1,%2,%3}, {%4,%5,%6,%7}, {%8,%9}, {%0,%1,%2,%3};"
        : "+f"(d[0]), "+f"(d[1]), "+f"(d[2]), "+f"(d[3])
        : "r"(a[0]), "r"(a[1]), "r"(a[2]), "r"(a[3]), "r"(b[0]), "r"(b[1]));
}

__device__ __forceinline__ void tf32_split(float f, uint32_t& hi, uint32_t& lo) {
    hi = __float_as_uint(f) & 0xFFFFE000u;
    float lf = f - __uint_as_float(hi);
    lo = __float_as_uint(lf) & 0xFFFFE000u;
}

// ---------------- GEMM: g_h = A[NN,256] @ B[256,256] via 3xTF32 tensor cores --------
__global__ void __launch_bounds__(256, 1)
gemm_tf32_kernel(const float* __restrict__ Ax, const float* __restrict__ B, int useFeat) {
    __shared__ float As[BK * BM];
    __shared__ float Bs[BK * BN];

    const float* A = useFeat ? g_feat : Ax;

    int tid  = threadIdx.x;
    int warp = tid >> 5;
    int lane = tid & 31;
    int wm = warp >> 1;
    int wn = warp & 1;
    int row0 = blockIdx.y * BM;
    int col0 = blockIdx.x * BN;
    int c = lane & 3;
    int r = lane >> 2;

    float acc[2][8][4];
#pragma unroll
    for (int mt = 0; mt < 2; mt++)
#pragma unroll
        for (int nt = 0; nt < 8; nt++)
#pragma unroll
            for (int i = 0; i < 4; i++) acc[mt][nt][i] = 0.f;

    int am = tid >> 1;
    int ak = (tid & 1) * 8;
    int bk = tid >> 4;
    int bn = (tid & 15) * 8;

    float4 pa0, pa1, pb0, pb1;
    {
        int grow = row0 + am;
        if (grow < NN) {
            pa0 = *(const float4*)&A[grow * F + ak];
            pa1 = *(const float4*)&A[grow * F + ak + 4];
        } else {
            pa0 = make_float4(0.f, 0.f, 0.f, 0.f);
            pa1 = pa0;
        }
        pb0 = *(const float4*)&B[bk * F + col0 + bn];
        pb1 = *(const float4*)&B[bk * F + col0 + bn + 4];
    }

    for (int k0 = 0; k0 < F; k0 += BK) {
        float av[8] = {pa0.x, pa0.y, pa0.z, pa0.w, pa1.x, pa1.y, pa1.z, pa1.w};
#pragma unroll
        for (int j = 0; j < 8; j++) {
            int kk = ak + j;
            As[kk * BM + (am ^ ((kk & 3) << 3))] = av[j];
        }
        *(float4*)&Bs[bk * BN + (bn ^ ((bk & 3) << 3))]       = pb0;
        *(float4*)&Bs[bk * BN + ((bn + 4) ^ ((bk & 3) << 3))] = pb1;
        __syncthreads();

        if (k0 + BK < F) {
            int kn = k0 + BK;
            int grow = row0 + am;
            if (grow < NN) {
                pa0 = *(const float4*)&A[grow * F + kn + ak];
                pa1 = *(const float4*)&A[grow * F + kn + ak + 4];
            } else {
                pa0 = make_float4(0.f, 0.f, 0.f, 0.f);
                pa1 = pa0;
            }
            pb0 = *(const float4*)&B[(kn + bk) * F + col0 + bn];
            pb1 = *(const float4*)&B[(kn + bk) * F + col0 + bn + 4];
        }

#pragma unroll
        for (int k8 = 0; k8 < 2; k8++) {
            int kb = k8 * 8;
            uint32_t aH[2][4], aL[2][4];
#pragma unroll
            for (int mt = 0; mt < 2; mt++) {
                int m0 = wm * 32 + mt * 16;
                int xr  = (m0 + r) ^ (c << 3);
                int xr8 = (m0 + r + 8) ^ (c << 3);
                float f0 = As[(kb + c) * BM + xr];
                float f1 = As[(kb + c) * BM + xr8];
                float f2 = As[(kb + c + 4) * BM + xr];
                float f3 = As[(kb + c + 4) * BM + xr8];
                tf32_split(f0, aH[mt][0], aL[mt][0]);
                tf32_split(f1, aH[mt][1], aL[mt][1]);
                tf32_split(f2, aH[mt][2], aL[mt][2]);
                tf32_split(f3, aH[mt][3], aL[mt][3]);
            }
#pragma unroll
            for (int nt = 0; nt < 8; nt++) {
                int n_ = wn * 64 + nt * 8 + r;
                int xn = n_ ^ (c << 3);
                float g0 = Bs[(kb + c) * BN + xn];
                float g1 = Bs[(kb + c + 4) * BN + xn];
                uint32_t bH[2], bL[2];
                tf32_split(g0, bH[0], bL[0]);
                tf32_split(g1, bH[1], bL[1]);
#pragma unroll
                for (int mt = 0; mt < 2; mt++) {
                    mma_tf32(acc[mt][nt], aH[mt], bH);
                    mma_tf32(acc[mt][nt], aH[mt], bL);
                    mma_tf32(acc[mt][nt], aL[mt], bH);
                }
            }
        }
        __syncthreads();
    }

#pragma unroll
    for (int mt = 0; mt < 2; mt++) {
        int rb = row0 + wm * 32 + mt * 16 + r;
#pragma unroll
        for (int nt = 0; nt < 8; nt++) {
            int cb = col0 + wn * 64 + nt * 8 + 2 * c;
            if (rb < NN)
                *(float2*)&g_h[rb * F + cb] = make_float2(acc[mt][nt][0], acc[mt][nt][1]);
            if (rb + 8 < NN)
                *(float2*)&g_h[(rb + 8) * F + cb] = make_float2(acc[mt][nt][2], acc[mt][nt][3]);
        }
    }
}

// ---------------- attention coefficients: a_src, a_dst per (node, head) ----------------
__global__ void attn_kernel(const float* __restrict__ att_src,
                            const float* __restrict__ att_dst) {
    int idx = blockIdx.x * blockDim.x + threadIdx.x;
    if (idx >= NN * HEADS) return;
    int n = idx >> 2;
    int h = idx & 3;
    const float4* hp = (const float4*)&g_h[n * F + h * CH];
    const float4* as = (const float4*)&att_src[h * CH];
    const float4* ad = (const float4*)&att_dst[h * CH];
    float ssum = 0.f, dsum = 0.f;
#pragma unroll
    for (int i = 0; i < 16; i++) {
        float4 v = hp[i];
        float4 s4 = as[i];
        float4 d4 = ad[i];
        ssum += v.x * s4.x + v.y * s4.y + v.z * s4.z + v.w * s4.w;
        dsum += v.x * d4.x + v.y * d4.y + v.z * d4.z + v.w * d4.w;
    }
    g_asrc[idx] = ssum;
    g_adst[idx] = dsum;
}

// ---------------- CSR build ----------------
__global__ void hist_zero_kernel() {
    int i = blockIdx.x * blockDim.x + threadIdx.x;
    if (i < NN) g_cnt[i] = 0;
}

__global__ void hist_kernel(const int* __restrict__ dst) {
    int e = blockIdx.x * blockDim.x + threadIdx.x;
    if (e < NE) atomicAdd(&g_cnt[dst[e]], 1);
}

// single-block exclusive scan over g_cnt -> g_start, g_cursor
__global__ void scan_kernel() {
    __shared__ int warp_sums[32];
    __shared__ int s_carry;
    int tid = threadIdx.x;
    int lane = tid & 31;
    int wid = tid >> 5;
    if (tid == 0) s_carry = 0;
    __syncthreads();
    for (int base = 0; base < NN; base += 1024) {
        int i = base + tid;
        int v = (i < NN) ? g_cnt[i] : 0;
        int x = v;
#pragma unroll
        for (int o = 1; o < 32; o <<= 1) {
            int y = __shfl_up_sync(0xffffffffu, x, o);
            if (lane >= o) x += y;
        }
        if (lane == 31) warp_sums[wid] = x;
        __syncthreads();
        if (wid == 0) {
            int ws = warp_sums[lane];
#pragma unroll
            for (int o = 1; o < 32; o <<= 1) {
                int y = __shfl_up_sync(0xffffffffu, ws, o);
                if (lane >= o) ws += y;
            }
            warp_sums[lane] = ws;
        }
        __syncthreads();
        int excl = x - v + (wid > 0 ? warp_sums[wid - 1] : 0) + s_carry;
        if (i < NN) { g_start[i] = excl; g_cursor[i] = excl; }
        __syncthreads();
        if (tid == 0) s_carry += warp_sums[31];
        __syncthreads();
    }
    if (tid == 0) g_start[NN] = s_carry;
}

__global__ void scatter_kernel(const int* __restrict__ src,
                               const int* __restrict__ dst) {
    int e = blockIdx.x * blockDim.x + threadIdx.x;
    if (e >= NE) return;
    int d = dst[e];
    int p = atomicAdd(&g_cursor[d], 1);
    g_csr_src[p] = src[e];
}

// ---------------- fused aggregation: warp per dst node, register accumulators ------
// out[d] = elu( (wself*h[d] + sum_e w_e*h[src_e]) / (wself + sum w_e + 1e-16) + bias )
__global__ void __launch_bounds__(256)
agg_kernel(const float* __restrict__ bias, float* __restrict__ outp, int toFeat) {
    int d = blockIdx.x * 8 + (threadIdx.x >> 5);
    if (d >= NN) return;
    int lane = threadIdx.x & 31;
    int h = lane >> 3;                      // head for this lane's 8 columns

    float adst_h = g_adst[d * 4 + h];
    float wself  = expf(lrelu(g_asrc[d * 4 + h] + adst_h));

    const float4* hp = (const float4*)&g_h[d * F + lane * 8];
    float4 a0 = hp[0], a1 = hp[1];
    float4 acc0 = make_float4(wself * a0.x, wself * a0.y, wself * a0.z, wself * a0.w);
    float4 acc1 = make_float4(wself * a1.x, wself * a1.y, wself * a1.z, wself * a1.w);
    float denom = wself;

    int s0 = g_start[d];
    int s1 = g_start[d + 1];

    for (int base = s0; base < s1; base += 32) {
        int cnt = min(32, s1 - base);
        int sidx = (lane < cnt) ? g_csr_src[base + lane] : 0;
        int nsub = (cnt + 7) >> 3;
        for (int sub = 0; sub < nsub; sub++) {
            // lanes compute weight for edge (sub*8 + lane&7), head (lane>>3)
            int sw = __shfl_sync(0xffffffffu, sidx, sub * 8 + (lane & 7));
            float wl = expf(lrelu(g_asrc[sw * 4 + h] + adst_h));
            int jend = min(8, cnt - sub * 8);
#pragma unroll 4
            for (int j = 0; j < jend; j++) {
                int s  = __shfl_sync(0xffffffffu, sidx, sub * 8 + j);
                float w = __shfl_sync(0xffffffffu, wl, (lane & 24) + j);
                const float4* sp = (const float4*)&g_h[s * F + lane * 8];
                float4 v0 = sp[0];
                float4 v1 = sp[1];
                acc0.x += w * v0.x; acc0.y += w * v0.y;
                acc0.z += w * v0.z; acc0.w += w * v0.w;
                acc1.x += w * v1.x; acc1.y += w * v1.y;
                acc1.z += w * v1.z; acc1.w += w * v1.w;
                denom += w;
            }
        }
    }

    float inv = 1.f / (denom + 1e-16f);
    float4 b0 = *(const float4*)&bias[lane * 8];
    float4 b1 = *(const float4*)&bias[lane * 8 + 4];
    acc0.x = elu1(acc0.x * inv + b0.x);
    acc0.y = elu1(acc0.y * inv + b0.y);
    acc0.z = elu1(acc0.z * inv + b0.z);
    acc0.w = elu1(acc0.w * inv + b0.w);
    acc1.x = elu1(acc1.x * inv + b1.x);
    acc1.y = elu1(acc1.y * inv + b1.y);
    acc1.z = elu1(acc1.z * inv + b1.z);
    acc1.w = elu1(acc1.w * inv + b1.w);

    float* dp = (toFeat ? g_feat : outp) + d * F + lane * 8;
    *(float4*)dp       = acc0;
    *(float4*)(dp + 4) = acc1;
}

// ---------------- launch ----------------
static void run_layer(const float* x_or_null, int useFeat,
                      const float* W, const float* att_src, const float* att_dst,
                      const float* bias, float* outp, int toFeat) {
    dim3 gemmGrid(F / BN, (NN + BM - 1) / BM);
    gemm_tf32_kernel<<<gemmGrid, 256>>>(x_or_null, W, useFeat);

    int nh = NN * HEADS;
    attn_kernel<<<(nh + 255) / 256, 256>>>(att_src, att_dst);
    agg_kernel<<<(NN + 7) / 8, 256>>>(bias, outp, toFeat);
}

extern "C" void kernel_launch(void* const* d_in, const int* in_sizes, int n_in,
                              void* d_out, int out_size) {
    const float* x        = (const float*)d_in[0];
    const int*   ei       = (const int*)  d_in[1];
    const float* W1       = (const float*)d_in[2];
    const float* att_src1 = (const float*)d_in[3];
    const float* att_dst1 = (const float*)d_in[4];
    const float* b1       = (const float*)d_in[5];
    const float* W2       = (const float*)d_in[6];
    const float* att_src2 = (const float*)d_in[7];
    const float* att_dst2 = (const float*)d_in[8];
    const float* b2       = (const float*)d_in[9];
    float* out = (float*)d_out;

    const int* src = ei;            // edge_index[0]
    const int* dst = ei + NE;       // edge_index[1]

    // CSR build (shared by both layers)
    hist_zero_kernel<<<(NN + 255) / 256, 256>>>();
    hist_kernel<<<(NE + 255) / 256, 256>>>(dst);
    scan_kernel<<<1, 1024>>>();
    scatter_kernel<<<(NE + 255) / 256, 256>>>(src, dst);

    // layer 1: x -> g_feat
    run_layer(x, 0, W1, att_src1, att_dst1, b1, nullptr, 1);
    // layer 2: g_feat -> out
    run_layer(nullptr, 1, W2, att_src2, att_dst2, b2, out, 0);
}